// round 15
// baseline (speedup 1.0000x reference)
#include <cuda_runtime.h>
#include <cstdint>
#include <cstddef>

#define NNET 16
#define BB   16
#define TT   512
#define II   256
#define HH   512
#define GROUPS 8          // CTAs per network; also h-channel slices of 64
#define OSL  64           // output channels per scan CTA
#define OUT_XP (NNET * BB * TT * HH)   // element offset of h_n section in d_out

// Persistent state: double-buffered h + per-(net,group) publication flags.
// flag[n][g] = v  means  slot v&1 holds h_v for channels of group g (net n).
__device__ float    g_hbuf[2][NNET][BB][HH];
__device__ unsigned g_flag[NNET][GROUPS][32];   // one 128B L2 line per flag

// ---------------------------------------------------------------------------
// f32x2 / memory helpers
// ---------------------------------------------------------------------------
__device__ __forceinline__ void fma2(uint64_t& acc, uint64_t a, uint64_t b) {
    asm("fma.rn.f32x2 %0, %1, %2, %0;" : "+l"(acc) : "l"(a), "l"(b));
}
__device__ __forceinline__ float hsum2(uint64_t v) {
    float lo, hi;
    asm("mov.b64 {%0, %1}, %2;" : "=f"(lo), "=f"(hi) : "l"(v));
    return lo + hi;
}
__device__ __forceinline__ void lds_v2u64(uint64_t& a, uint64_t& b, unsigned saddr) {
    asm("ld.shared.v2.b64 {%0, %1}, [%2];" : "=l"(a), "=l"(b) : "r"(saddr));
}
__device__ __forceinline__ void ldg_nc_v2u64(uint64_t& a, uint64_t& b, const float* p) {
    asm("ld.global.nc.v2.b64 {%0, %1}, [%2];" : "=l"(a), "=l"(b) : "l"(p));
}
__device__ __forceinline__ unsigned ld_acq_gpu(const unsigned* p) {
    unsigned v;
    asm volatile("ld.acquire.gpu.global.u32 %0, [%1];" : "=r"(v) : "l"(p) : "memory");
    return v;
}
__device__ __forceinline__ void st_rel_gpu(unsigned* p, unsigned v) {
    asm volatile("st.release.gpu.global.u32 [%0], %1;" :: "l"(p), "r"(v) : "memory");
}

// ---------------------------------------------------------------------------
// Phase 1: x_proj (unchanged — ~0.89ms, ~54% of FFMA2 issue floor)
// ---------------------------------------------------------------------------
__global__ __launch_bounds__(256, 2) void xproj_kernel(
    const float* __restrict__ x, const float* __restrict__ w_ih,
    const float* __restrict__ b_ih, float* __restrict__ out)
{
    __shared__ float As[128][20];
    __shared__ float Ws[64][20];

    const int tid = threadIdx.x;
    const int net = blockIdx.z;
    const int bm  = blockIdx.x * 128;
    const int bn  = blockIdx.y * 64;
    const int tx  = tid & 15;
    const int ty  = tid >> 4;

    const float* xA = x    + (size_t)net * BB * TT * II + (size_t)bm * II;
    const float* xW = w_ih + (size_t)net * HH * II      + (size_t)bn * II;

    uint64_t acc[8][4];
#pragma unroll
    for (int i = 0; i < 8; i++)
#pragma unroll
        for (int j = 0; j < 4; j++) acc[i][j] = 0ull;

    const int arow = tid >> 2, ac4 = tid & 3;
    const int wrow = tid >> 2, wc4 = tid & 3;

    for (int kt = 0; kt < II; kt += 16) {
        float4 a0 = *(const float4*)(xA + (size_t)arow        * II + kt + ac4 * 4);
        float4 a1 = *(const float4*)(xA + (size_t)(arow + 64) * II + kt + ac4 * 4);
        float4 w0 = *(const float4*)(xW + (size_t)wrow        * II + kt + wc4 * 4);
        __syncthreads();
        *(float4*)&As[arow][ac4 * 4]      = a0;
        *(float4*)&As[arow + 64][ac4 * 4] = a1;
        *(float4*)&Ws[wrow][wc4 * 4]      = w0;
        __syncthreads();
#pragma unroll
        for (int kk = 0; kk < 16; kk += 4) {
            uint64_t wv[4][2];
#pragma unroll
            for (int ni = 0; ni < 4; ni++) {
                unsigned sa = (unsigned)__cvta_generic_to_shared(&Ws[tx + ni * 16][kk]);
                lds_v2u64(wv[ni][0], wv[ni][1], sa);
            }
#pragma unroll
            for (int mi = 0; mi < 8; mi++) {
                uint64_t a01, a23;
                unsigned sa = (unsigned)__cvta_generic_to_shared(&As[ty * 8 + mi][kk]);
                lds_v2u64(a01, a23, sa);
#pragma unroll
                for (int ni = 0; ni < 4; ni++) {
                    fma2(acc[mi][ni], a01, wv[ni][0]);
                    fma2(acc[mi][ni], a23, wv[ni][1]);
                }
            }
        }
    }

    float bias[4];
#pragma unroll
    for (int ni = 0; ni < 4; ni++) bias[ni] = b_ih[net * HH + bn + tx + ni * 16];

    float* orow = out + (size_t)net * BB * TT * HH + (size_t)(bm + ty * 8) * HH + bn;
#pragma unroll
    for (int mi = 0; mi < 8; mi++)
#pragma unroll
        for (int ni = 0; ni < 4; ni++)
            orow[(size_t)mi * HH + tx + ni * 16] = hsum2(acc[mi][ni]) + bias[ni];
}

// ---------------------------------------------------------------------------
// Phase 2: persistent scan with fine-grained producer flags, on R11's proven
// 512-thread geometry (regs ~= R11's 128, which compiled & ran).
// 128 CTAs = 16 nets x 8 groups; CTA owns channels [64*grp, 64*grp+64) x 16 b.
// 16 warps = 2 ogrp x 8 ksp; lane = 1 channel; wreg[32] per thread.
// Warp-pair ksp: waits only on flag[n][ksp], stages only slice
// h[:, 64*ksp..64*ksp+64) (2KB per warp), syncs via named barrier, computes.
// ---------------------------------------------------------------------------
__global__ __launch_bounds__(512, 1) void rnn_scan_kernel(
    const float* __restrict__ w_hh, const float* __restrict__ b_hh,
    float* __restrict__ out)
{
    __shared__ float h_s[GROUPS][BB][64];     // 32 KB: slice-major staged h
    __shared__ float red[GROUPS][BB * OSL];   // 32 KB: k-split partials

    const int tid   = threadIdx.x;
    const int n     = blockIdx.x >> 3;
    const int grp   = blockIdx.x & 7;
    const int wid   = tid >> 5, lane = tid & 31;
    const int ogrp  = wid & 1,  ksp  = wid >> 1;   // ksp in 0..7
    const int o_loc = ogrp * 32 + lane;
    const int o_glb = grp * OSL + o_loc;
    const int kbase = ksp * 64;
    const int pairtid = ogrp * 32 + lane;          // 0..63 within the ksp pair

    const float* wrow = w_hh + ((size_t)n * HH + o_glb) * HH + kbase;
    float* hb = &g_hbuf[0][0][0][0];
    const unsigned SLAB = NNET * BB * HH;
    const unsigned* flg = &g_flag[n][ksp][0];      // our slice's producer
    unsigned* myflg = &g_flag[n][grp][0];          // our publication

    // Hoist this thread's 64 w_hh values (1 channel x k-slice) into registers.
    uint64_t wreg[32];
#pragma unroll
    for (int j = 0; j < 16; j++)
        ldg_nc_v2u64(wreg[2 * j], wreg[2 * j + 1], wrow + 4 * j);

    // Per-thread epilogue constants: outputs j = r*512 + tid (j = b*64 + oo).
    float    bh[2];
    unsigned xoff[2], hoff[2];
#pragma unroll
    for (int r = 0; r < 2; r++) {
        int j = (r << 9) + tid;
        int b = j >> 6, oo = j & 63;
        int og = grp * OSL + oo;
        bh[r]   = b_hh[n * HH + og];
        xoff[r] = (unsigned)((n * BB + b) * TT * HH + og);
        hoff[r] = (unsigned)((n * BB + b) * HH + og);
    }

    const unsigned hsbase = (unsigned)__cvta_generic_to_shared(&h_s[ksp][0][0]);

    for (int t = 0; t < TT; ++t) {
        const int p = t & 1;

        // Prefetch this step's x_proj values (independent; fills spin window).
        float xv[2];
#pragma unroll
        for (int r = 0; r < 2; r++) xv[r] = out[xoff[r] + (unsigned)t * HH];

        // Wait for OUR slice's producer only (uniform acquire poll; monotonic).
        if (ld_acq_gpu(flg) < (unsigned)t) {
            while (ld_acq_gpu(flg) < (unsigned)t) { __nanosleep(32); }
        }

        // Pair-stage our 4KB slice (256 float4, 64 threads -> 4 each).
        {
            const float* src = hb + (unsigned)p * SLAB + (unsigned)(n * BB * HH) + kbase;
#pragma unroll
            for (int u = 0; u < 4; u++) {
                int fidx = u * 64 + pairtid;       // 0..255
                int b = fidx >> 4, c4 = fidx & 15;
                float4 v = __ldcg((const float4*)(src + b * HH) + c4);
                ((float4*)&h_s[ksp][b][0])[c4] = v;
            }
        }
        asm volatile("bar.sync %0, 64;" :: "r"(ksp + 1) : "memory");  // pair sync

        // Slice GEMM: acc[b] += h[b][kbase..] * wreg[..]; 2 FFMA2 per LDS.128.
        uint64_t acc[16];
#pragma unroll
        for (int b = 0; b < 16; b++) acc[b] = 0ull;
#pragma unroll
        for (int kk = 0; kk < 16; kk++) {
            const uint64_t w01 = wreg[2 * kk];
            const uint64_t w23 = wreg[2 * kk + 1];
#pragma unroll
            for (int b = 0; b < 16; b++) {
                uint64_t h01, h23;
                lds_v2u64(h01, h23, hsbase + b * 256 + kk * 16);
                fma2(acc[b], h01, w01);
                fma2(acc[b], h23, w23);
            }
        }

        // Partials: red[ksp][b*64 + o_loc] (og halves disjoint, conflict-free).
#pragma unroll
        for (int b = 0; b < 16; b++)
            red[ksp][(b << 6) | o_loc] = hsum2(acc[b]);
        __syncthreads();                         // all slices' partials in

        // Reduce 8 partials, + bias + x_proj, tanh; publish h first.
        const int pnew = (t + 1) & 1;
        float hv[2];
#pragma unroll
        for (int r = 0; r < 2; r++) {
            int j = (r << 9) + tid;
            float s = bh[r];
#pragma unroll
            for (int q = 0; q < 8; q++) s += red[q][j];
            hv[r] = tanhf(xv[r] + s);
            hb[(unsigned)pnew * SLAB + hoff[r]] = hv[r];
        }
        __threadfence();
        __syncthreads();                         // all h stores fenced

        // Publish our flag (release), then off-critical-path out[] stores.
        if (tid == 0) st_rel_gpu(myflg, (unsigned)(t + 1));
#pragma unroll
        for (int r = 0; r < 2; r++) {
            out[xoff[r] + (unsigned)t * HH] = hv[r];
            if (t == TT - 1) out[OUT_XP + hoff[r]] = hv[r];
        }
        // No trailing barrier needed: next-step writes to h_s[ksp] / red[ksp]
        // occur after this step's post-fence __syncthreads (program order),
        // which globally follows all reads of those regions.
    }
}

// ---------------------------------------------------------------------------
// Launch. Inputs (metadata order): x, w_ih, w_hh, b_ih, b_hh. Output: fp32
// concat(output[N,B,T,H], h_n[N,B,H]).
// ---------------------------------------------------------------------------
extern "C" void kernel_launch(void* const* d_in, const int* in_sizes, int n_in,
                              void* d_out, int out_size)
{
    (void)in_sizes; (void)n_in; (void)out_size;
    const float* x    = (const float*)d_in[0];
    const float* w_ih = (const float*)d_in[1];
    const float* w_hh = (const float*)d_in[2];
    const float* b_ih = (const float*)d_in[3];
    const float* b_hh = (const float*)d_in[4];
    float* out = (float*)d_out;

    void* hb = nullptr;  void* fp = nullptr;
    cudaGetSymbolAddress(&hb, g_hbuf);
    cudaGetSymbolAddress(&fp, g_flag);
    cudaMemsetAsync(hb, 0, sizeof(float) * NNET * BB * HH, 0);        // h0 slot
    cudaMemsetAsync(fp, 0, sizeof(unsigned) * NNET * GROUPS * 32, 0); // flags

    dim3 g1(TT * BB / 128, HH / 64, NNET);   // 64 x 8 x 16
    xproj_kernel<<<g1, 256>>>(x, w_ih, b_ih, out);

    rnn_scan_kernel<<<NNET * GROUPS, 512>>>(w_hh, b_hh, out);
}

// round 16
// speedup vs baseline: 1.2215x; 1.2215x over previous
#include <cuda_runtime.h>
#include <cstdint>
#include <cstddef>

#define NNET 16
#define BB   16
#define TT   512
#define II   256
#define HH   512
#define GROUPS 8          // CTAs per network; also h k-slices of 64
#define OSL  64           // output channels per scan CTA
#define OUT_XP (NNET * BB * TT * HH)   // element offset of h_n section in d_out

// Persistent state: double-buffered h + per-(net,group) publication flags.
__device__ float    g_hbuf[2][NNET][BB][HH];
__device__ unsigned g_flag[NNET][GROUPS][32];   // one 128B L2 line per flag

// ---------------------------------------------------------------------------
// f32x2 / memory helpers
// ---------------------------------------------------------------------------
__device__ __forceinline__ void fma2(uint64_t& acc, uint64_t a, uint64_t b) {
    asm("fma.rn.f32x2 %0, %1, %2, %0;" : "+l"(acc) : "l"(a), "l"(b));
}
__device__ __forceinline__ float hsum2(uint64_t v) {
    float lo, hi;
    asm("mov.b64 {%0, %1}, %2;" : "=f"(lo), "=f"(hi) : "l"(v));
    return lo + hi;
}
__device__ __forceinline__ void lds_v2u64(uint64_t& a, uint64_t& b, unsigned saddr) {
    asm("ld.shared.v2.b64 {%0, %1}, [%2];" : "=l"(a), "=l"(b) : "r"(saddr));
}
__device__ __forceinline__ void ldg_nc_v2u64(uint64_t& a, uint64_t& b, const float* p) {
    asm("ld.global.nc.v2.b64 {%0, %1}, [%2];" : "=l"(a), "=l"(b) : "l"(p));
}
__device__ __forceinline__ unsigned ld_acq_gpu(const unsigned* p) {
    unsigned v;
    asm volatile("ld.acquire.gpu.global.u32 %0, [%1];" : "=r"(v) : "l"(p) : "memory");
    return v;
}
__device__ __forceinline__ void st_rel_gpu(unsigned* p, unsigned v) {
    asm volatile("st.release.gpu.global.u32 [%0], %1;" :: "l"(p), "r"(v) : "memory");
}

// ---------------------------------------------------------------------------
// Phase 1: x_proj (unchanged — ~0.89ms, ~54% of FFMA2 issue floor)
// ---------------------------------------------------------------------------
__global__ __launch_bounds__(256, 2) void xproj_kernel(
    const float* __restrict__ x, const float* __restrict__ w_ih,
    const float* __restrict__ b_ih, float* __restrict__ out)
{
    __shared__ float As[128][20];
    __shared__ float Ws[64][20];

    const int tid = threadIdx.x;
    const int net = blockIdx.z;
    const int bm  = blockIdx.x * 128;
    const int bn  = blockIdx.y * 64;
    const int tx  = tid & 15;
    const int ty  = tid >> 4;

    const float* xA = x    + (size_t)net * BB * TT * II + (size_t)bm * II;
    const float* xW = w_ih + (size_t)net * HH * II      + (size_t)bn * II;

    uint64_t acc[8][4];
#pragma unroll
    for (int i = 0; i < 8; i++)
#pragma unroll
        for (int j = 0; j < 4; j++) acc[i][j] = 0ull;

    const int arow = tid >> 2, ac4 = tid & 3;
    const int wrow = tid >> 2, wc4 = tid & 3;

    for (int kt = 0; kt < II; kt += 16) {
        float4 a0 = *(const float4*)(xA + (size_t)arow        * II + kt + ac4 * 4);
        float4 a1 = *(const float4*)(xA + (size_t)(arow + 64) * II + kt + ac4 * 4);
        float4 w0 = *(const float4*)(xW + (size_t)wrow        * II + kt + wc4 * 4);
        __syncthreads();
        *(float4*)&As[arow][ac4 * 4]      = a0;
        *(float4*)&As[arow + 64][ac4 * 4] = a1;
        *(float4*)&Ws[wrow][wc4 * 4]      = w0;
        __syncthreads();
#pragma unroll
        for (int kk = 0; kk < 16; kk += 4) {
            uint64_t wv[4][2];
#pragma unroll
            for (int ni = 0; ni < 4; ni++) {
                unsigned sa = (unsigned)__cvta_generic_to_shared(&Ws[tx + ni * 16][kk]);
                lds_v2u64(wv[ni][0], wv[ni][1], sa);
            }
#pragma unroll
            for (int mi = 0; mi < 8; mi++) {
                uint64_t a01, a23;
                unsigned sa = (unsigned)__cvta_generic_to_shared(&As[ty * 8 + mi][kk]);
                lds_v2u64(a01, a23, sa);
#pragma unroll
                for (int ni = 0; ni < 4; ni++) {
                    fma2(acc[mi][ni], a01, wv[ni][0]);
                    fma2(acc[mi][ni], a23, wv[ni][1]);
                }
            }
        }
    }

    float bias[4];
#pragma unroll
    for (int ni = 0; ni < 4; ni++) bias[ni] = b_ih[net * HH + bn + tx + ni * 16];

    float* orow = out + (size_t)net * BB * TT * HH + (size_t)(bm + ty * 8) * HH + bn;
#pragma unroll
    for (int mi = 0; mi < 8; mi++)
#pragma unroll
        for (int ni = 0; ni < 4; ni++)
            orow[(size_t)mi * HH + tx + ni * 16] = hsum2(acc[mi][ni]) + bias[ni];
}

// ---------------------------------------------------------------------------
// Phase 2: persistent scan. 128 CTAs = 16 nets x 8 groups; CTA owns channels
// [64*grp, 64*grp+64) x 16 batches. 256 threads, 8 warps; warp w = k-slice w.
// TWO channels per lane (halves LDS instruction count AND L1 writeback bytes
// vs the 1-ch/lane builds that all plateaued at ~12.7K cyc/step), with the
// b-loop split in two halves of 8 so accumulators stay at 32 regs (defusing
// the ~250-reg build that hung R12/R13). Fine-grained producer flags kept.
// ---------------------------------------------------------------------------
__global__ __launch_bounds__(256, 1) void rnn_scan_kernel(
    const float* __restrict__ w_hh, const float* __restrict__ b_hh,
    float* __restrict__ out)
{
    __shared__ float h_s[GROUPS][BB][64];     // 32 KB: per-warp staged k-slice
    __shared__ float red[GROUPS][BB * OSL];   // 32 KB: per-slice partials

    const int tid  = threadIdx.x;
    const int n    = blockIdx.x >> 3;
    const int grp  = blockIdx.x & 7;
    const int wid  = tid >> 5, lane = tid & 31;
    const int kbase = wid * 64;               // k-slice = source group wid

    // This lane's 2 adjacent output channels (STS.64 partial packing).
    const int o0 = grp * OSL + 2 * lane;

    float* hb = &g_hbuf[0][0][0][0];
    const unsigned SLAB = NNET * BB * HH;
    const unsigned* flg = &g_flag[n][wid][0];  // our slice's producer
    unsigned* myflg = &g_flag[n][grp][0];      // our publication

    // Hoist w_hh rows o0, o0+1 (k-slice only: 64 floats each) into registers.
    uint64_t wA[32], wB[32];
    {
        const float* r0 = w_hh + ((size_t)n * HH + o0)     * HH + kbase;
        const float* r1 = w_hh + ((size_t)n * HH + o0 + 1) * HH + kbase;
#pragma unroll
        for (int j = 0; j < 16; j++) {
            ldg_nc_v2u64(wA[2 * j], wA[2 * j + 1], r0 + 4 * j);
            ldg_nc_v2u64(wB[2 * j], wB[2 * j + 1], r1 + 4 * j);
        }
    }

    // Per-thread epilogue constants: outputs j = r*256 + tid (j = b*64 + oo).
    float    bh[4];
    unsigned xoff[4], hoff[4];
#pragma unroll
    for (int r = 0; r < 4; r++) {
        int j = (r << 8) + tid;
        int b = j >> 6, oo = j & 63;
        int og = grp * OSL + oo;
        bh[r]   = b_hh[n * HH + og];
        xoff[r] = (unsigned)((n * BB + b) * TT * HH + og);
        hoff[r] = (unsigned)((n * BB + b) * HH + og);
    }

    const unsigned hsbase = (unsigned)__cvta_generic_to_shared(&h_s[wid][0][0]);

    for (int t = 0; t < TT; ++t) {
        const int p = t & 1;

        // Prefetch this step's x_proj values (independent; fills spin window).
        float xv[4];
#pragma unroll
        for (int r = 0; r < 4; r++) xv[r] = out[xoff[r] + (unsigned)t * HH];

        // Wait for OUR slice's producer only (uniform acquire poll; monotonic).
        if (ld_acq_gpu(flg) < (unsigned)t) {
            while (ld_acq_gpu(flg) < (unsigned)t) { __nanosleep(32); }
        }

        // Stage our 4KB slice: h[b][kbase..kbase+64) for all 16 b (warp-only).
        {
            const float* src = hb + (unsigned)p * SLAB + (unsigned)(n * BB * HH) + kbase;
#pragma unroll
            for (int u = 0; u < 8; u++) {
                int fidx = u * 32 + lane;          // 256 float4s in the slice
                int b = fidx >> 4, c4 = fidx & 15;
                float4 v = __ldcg((const float4*)(src + b * HH) + c4);
                ((float4*)&h_s[wid][b][0])[c4] = v;
            }
        }
        __syncwarp();

        // Slice GEMM in two b-halves (acc stays at 32 regs):
        // per (kk, b): 1 broadcast LDS.128 feeds 4 FFMA2 (2 channels).
#pragma unroll
        for (int half = 0; half < 2; half++) {
            uint64_t accA[8], accB[8];
#pragma unroll
            for (int b = 0; b < 8; b++) { accA[b] = 0ull; accB[b] = 0ull; }
            const unsigned hb8 = hsbase + (unsigned)(half * 8 * 256);
#pragma unroll
            for (int kk = 0; kk < 16; kk++) {
                const uint64_t a0 = wA[2 * kk], a1 = wA[2 * kk + 1];
                const uint64_t b0 = wB[2 * kk], b1 = wB[2 * kk + 1];
#pragma unroll
                for (int b = 0; b < 8; b++) {
                    uint64_t h01, h23;
                    lds_v2u64(h01, h23, hb8 + b * 256 + kk * 16);
                    fma2(accA[b], h01, a0);
                    fma2(accA[b], h23, a1);
                    fma2(accB[b], h01, b0);
                    fma2(accB[b], h23, b1);
                }
            }
            // Partials: red[wid][b*64 + 2*lane .. +1] (STS.64, conflict-free).
#pragma unroll
            for (int b = 0; b < 8; b++)
                *(float2*)&red[wid][((half * 8 + b) << 6) | (2 * lane)] =
                    make_float2(hsum2(accA[b]), hsum2(accB[b]));
        }
        __syncthreads();                         // all slices' partials in

        // Reduce 8 partials, + bias + x_proj, tanh; publish h first.
        const int pnew = (t + 1) & 1;
        float hv[4];
#pragma unroll
        for (int r = 0; r < 4; r++) {
            int j = (r << 8) + tid;
            float s = bh[r];
#pragma unroll
            for (int q = 0; q < 8; q++) s += red[q][j];
            hv[r] = tanhf(xv[r] + s);
            hb[(unsigned)pnew * SLAB + hoff[r]] = hv[r];
        }
        __threadfence();
        __syncthreads();                         // all h stores fenced

        // Publish our flag (release), then off-critical-path out[] stores.
        if (tid == 0) st_rel_gpu(myflg, (unsigned)(t + 1));
#pragma unroll
        for (int r = 0; r < 4; r++) {
            out[xoff[r] + (unsigned)t * HH] = hv[r];
            if (t == TT - 1) out[OUT_XP + hoff[r]] = hv[r];
        }
        // No trailing barrier: h_s[wid]/red[wid] next-step writes occur after
        // this step's post-fence __syncthreads, which follows all their reads.
    }
}

// ---------------------------------------------------------------------------
// Launch. Inputs (metadata order): x, w_ih, w_hh, b_ih, b_hh. Output: fp32
// concat(output[N,B,T,H], h_n[N,B,H]).
// ---------------------------------------------------------------------------
extern "C" void kernel_launch(void* const* d_in, const int* in_sizes, int n_in,
                              void* d_out, int out_size)
{
    (void)in_sizes; (void)n_in; (void)out_size;
    const float* x    = (const float*)d_in[0];
    const float* w_ih = (const float*)d_in[1];
    const float* w_hh = (const float*)d_in[2];
    const float* b_ih = (const float*)d_in[3];
    const float* b_hh = (const float*)d_in[4];
    float* out = (float*)d_out;

    void* hb = nullptr;  void* fp = nullptr;
    cudaGetSymbolAddress(&hb, g_hbuf);
    cudaGetSymbolAddress(&fp, g_flag);
    cudaMemsetAsync(hb, 0, sizeof(float) * NNET * BB * HH, 0);        // h0 slot
    cudaMemsetAsync(fp, 0, sizeof(unsigned) * NNET * GROUPS * 32, 0); // flags

    dim3 g1(TT * BB / 128, HH / 64, NNET);   // 64 x 8 x 16
    xproj_kernel<<<g1, 256>>>(x, w_ih, b_ih, out);

    rnn_scan_kernel<<<NNET * GROUPS, 256>>>(w_hh, b_hh, out);
}